// round 6
// baseline (speedup 1.0000x reference)
#include <cuda_runtime.h>
#include <cstdint>

// CognitiveLorenzField: vL stays parallel to vL0, vJ stays in span{vL0,vJ0}.
// 500-step dynamics collapses to a scalar recurrence (a,b,c) driven by the
// Lorenz z. Output is rank-1/rank-2 expansion -> pure store bandwidth.
//
// R6: remove the per-iteration L2 table load from the store loop. Each warp
// loads the chunk's 10 float4 coefficients once (lanes 0-9, one L2 trip) and
// broadcasts them per-step via __shfl_sync. Store loop = pure FMA + STG.

#define DIM       65536
#define STEPS     500
#define CHUNK     10
#define TCHUNKS   (STEPS / CHUNK)       // 50
#define NSLICE    32                    // slices of 2048 floats (8KB)
#define NTILES    (TCHUNKS * NSLICE)    // 1600
#define NT        256
#define WRITERS   592                   // 4 CTA/SM
#define RBLK      64                    // reduction blocks

__device__ float4 g_tab[STEPS];         // (a, b, c, z) per step
__device__ int    g_flag[TCHUNKS];      // per-chunk ready flags
__device__ float  g_pP[RBLK], g_pQ[RBLK];

__device__ __forceinline__ void flag_release(int* p, int v) {
    asm volatile("st.release.gpu.global.s32 [%0], %1;" :: "l"(p), "r"(v) : "memory");
}
__device__ __forceinline__ int flag_acquire(const int* p) {
    int v;
    asm volatile("ld.acquire.gpu.global.s32 %0, [%1];" : "=r"(v) : "l"(p) : "memory");
    return v;
}

// ---- pre-kernel: per-block deterministic partial dots + flag reset ----
__global__ __launch_bounds__(NT)
void clf_pre(const float* __restrict__ vL, const float* __restrict__ vJ)
{
    const float4* vL4 = (const float4*)vL;
    const float4* vJ4 = (const float4*)vJ;
    int b = blockIdx.x;
    int k = b * NT + threadIdx.x;       // one float4 per thread, 1024 floats/block

    float4 l = vL4[k];
    float4 j = vJ4[k];
    float p = l.x * l.x + l.y * l.y + l.z * l.z + l.w * l.w;
    float q = l.x * j.x + l.y * j.y + l.z * j.z + l.w * j.w;

    #pragma unroll
    for (int off = 16; off > 0; off >>= 1) {
        p += __shfl_down_sync(0xffffffffu, p, off);
        q += __shfl_down_sync(0xffffffffu, q, off);
    }
    __shared__ float sp[8], sq[8];
    int wid = threadIdx.x >> 5, lid = threadIdx.x & 31;
    if (lid == 0) { sp[wid] = p; sq[wid] = q; }
    __syncthreads();
    if (threadIdx.x == 0) {
        float P = 0.0f, Q = 0.0f;
        #pragma unroll
        for (int i = 0; i < 8; i++) { P += sp[i]; Q += sq[i]; }
        g_pP[b] = P;
        g_pQ[b] = Q;
    }
    if (b == 0 && threadIdx.x < TCHUNKS)
        g_flag[threadIdx.x] = 0;        // re-arm for this graph replay
}

// ---- fused producer + persistent writers ----
__global__ __launch_bounds__(NT)
void clf_main(const float* __restrict__ vL,
              const float* __restrict__ vJ,
              float* __restrict__ out)
{
    const float dt = 0.01f;

    if (blockIdx.x == 0) {
        // -------- producer (single thread scalar recurrence) --------
        if (threadIdx.x == 0) {
            float P = 0.0f, Q = 0.0f;
            #pragma unroll
            for (int i = 0; i < RBLK; i++) { P += g_pP[i]; Q += g_pQ[i]; }

            float x = 1.0f, y = 1.0f, z = 1.0f;
            float a = 1.0f, b = 0.0f, c = 1.0f;  // vL=a*vL0 ; vJ=b*vL0+c*vJ0
            float* out_z = out + 2ull * STEPS * DIM;

            for (int t = 0; t < STEPS; t++) {
                // Lorenz Euler step (reference op order)
                float dx = 10.0f * (y - x);
                float dy = x * (28.0f - z) - y;
                float dz = x * y - (float)(8.0 / 3.0) * z;
                x += dt * dx;
                y += dt * dy;
                z += dt * dz;
                float alpha = 1.0f + 0.5f * z;

                // scalarized vector dynamics (keeps eps exactly as reference)
                float dot = a * (b * P + c * Q);
                float nsq = a * a * P + 1e-8f;
                float r   = __fdividef(dot, nsq);

                float an = a + dt * (alpha * ((r - 1.0f) * a) + 0.2f * a);
                float bn = b + dt * (alpha * (r * a - b) + 0.2f * (a - b));
                float cn = c + dt * (alpha * (-c) + 0.2f * (-c));
                a = an; b = bn; c = cn;

                __stcg(&g_tab[t], make_float4(a, b, c, z));  // L2-direct
                __stcg(&out_z[t], z);

                if (((t + 1) % CHUNK) == 0)
                    flag_release(&g_flag[t / CHUNK], 1);  // release: orders table stores
            }
        }
        return;
    }

    // -------- persistent writers (2 float4 per thread, 8KB tiles) --------
    int w    = blockIdx.x - 1;
    int lane = threadIdx.x & 31;
    const float4* vL4 = (const float4*)vL;
    const float4* vJ4 = (const float4*)vJ;
    float4* outL4 = (float4*)out;
    float4* outJ4 = outL4 + (size_t)STEPS * (DIM / 4);

    for (int tt = w; tt < NTILES; tt += WRITERS) {
        int chunk = tt / NSLICE;        // chunk-major tile order
        int slice = tt - chunk * NSLICE;
        int f0    = slice * (NT * 2) + threadIdx.x;  // two coalesced groups

        float4 l0 = __ldg(vL4 + f0);
        float4 j0 = __ldg(vJ4 + f0);
        float4 l1 = __ldg(vL4 + f0 + NT);
        float4 j1 = __ldg(vJ4 + f0 + NT);

        if (threadIdx.x == 0) {
            while (flag_acquire(&g_flag[chunk]) == 0)
                __nanosleep(128);
        }
        __syncthreads();                // broadcasts thread0's acquire to the CTA

        // One parallel L2 trip per warp: lane u holds step u's (a,b,c,z).
        float4 tv = make_float4(0.f, 0.f, 0.f, 0.f);
        if (lane < CHUNK)
            tv = __ldcg(&g_tab[chunk * CHUNK + lane]);

        #pragma unroll
        for (int u = 0; u < CHUNK; u++) {
            float a = __shfl_sync(0xffffffffu, tv.x, u);
            float b = __shfl_sync(0xffffffffu, tv.y, u);
            float c = __shfl_sync(0xffffffffu, tv.z, u);

            float4 oL0 = make_float4(a * l0.x, a * l0.y, a * l0.z, a * l0.w);
            float4 oL1 = make_float4(a * l1.x, a * l1.y, a * l1.z, a * l1.w);
            float4 oJ0 = make_float4(fmaf(b, l0.x, c * j0.x),
                                     fmaf(b, l0.y, c * j0.y),
                                     fmaf(b, l0.z, c * j0.z),
                                     fmaf(b, l0.w, c * j0.w));
            float4 oJ1 = make_float4(fmaf(b, l1.x, c * j1.x),
                                     fmaf(b, l1.y, c * j1.y),
                                     fmaf(b, l1.z, c * j1.z),
                                     fmaf(b, l1.w, c * j1.w));

            size_t base = (size_t)(chunk * CHUNK + u) * (DIM / 4) + f0;
            __stcs(&outL4[base],      oL0);
            __stcs(&outL4[base + NT], oL1);
            __stcs(&outJ4[base],      oJ0);
            __stcs(&outJ4[base + NT], oJ1);
        }
    }
}

extern "C" void kernel_launch(void* const* d_in, const int* in_sizes, int n_in,
                              void* d_out, int out_size)
{
    const float* vL = (const float*)d_in[0];
    const float* vJ = (const float*)d_in[1];
    float* out = (float*)d_out;

    clf_pre<<<RBLK, NT>>>(vL, vJ);
    clf_main<<<1 + WRITERS, NT>>>(vL, vJ, out);
}

// round 7
// speedup vs baseline: 1.0531x; 1.0531x over previous
#include <cuda_runtime.h>
#include <cstdint>

// CognitiveLorenzField: vL stays parallel to vL0, vJ stays in span{vL0,vJ0}.
// Dynamics collapse to a scalar recurrence; moreover r only appears as r*a,
// and r*a = b + c*(Q/P) exactly in fp32 (eps is below ulp of a^2*P), so the
// recurrence is DIVISION-FREE (~22 cyc/step). Lorenz alpha sequence is
// input-independent -> precomputed in the pre-kernel.
//
// R7: no producer, no flags, no spins. Every writer block replays the cheap
// recurrence in registers (alpha from smem) and streams its tiles.

#define DIM       65536
#define STEPS     500
#define CHUNK     10
#define TCHUNKS   (STEPS / CHUNK)       // 50
#define NSLICE    32                    // slices of 2048 floats (8KB)
#define NTILES    (TCHUNKS * NSLICE)    // 1600
#define NT        256
#define WRITERS   592                   // 4 CTA/SM
#define RBLK      64                    // reduction blocks

__device__ float g_alpha[STEPS];
__device__ float g_pP[RBLK], g_pQ[RBLK];

// ---- pre-kernel: P,Q partials (blocks 0..63) + Lorenz/alpha/z (block 64) ----
__global__ __launch_bounds__(NT)
void clf_pre(const float* __restrict__ vL, const float* __restrict__ vJ,
             float* __restrict__ out)
{
    if (blockIdx.x == RBLK) {
        if (threadIdx.x == 0) {
            const float dt = 0.01f;
            float x = 1.0f, y = 1.0f, z = 1.0f;
            float* out_z = out + 2ull * STEPS * DIM;
            for (int t = 0; t < STEPS; t++) {
                float dx = 10.0f * (y - x);
                float dy = x * (28.0f - z) - y;
                float dz = x * y - (float)(8.0 / 3.0) * z;
                x += dt * dx;
                y += dt * dy;
                z += dt * dz;
                g_alpha[t] = 1.0f + 0.5f * z;
                out_z[t]   = z;
            }
        }
        return;
    }

    const float4* vL4 = (const float4*)vL;
    const float4* vJ4 = (const float4*)vJ;
    int b = blockIdx.x;
    int k = b * NT + threadIdx.x;        // one float4/thread, 1024 floats/block

    float4 l = vL4[k];
    float4 j = vJ4[k];
    float p = l.x * l.x + l.y * l.y + l.z * l.z + l.w * l.w;
    float q = l.x * j.x + l.y * j.y + l.z * j.z + l.w * j.w;

    #pragma unroll
    for (int off = 16; off > 0; off >>= 1) {
        p += __shfl_down_sync(0xffffffffu, p, off);
        q += __shfl_down_sync(0xffffffffu, q, off);
    }
    __shared__ float sp[8], sq[8];
    int wid = threadIdx.x >> 5, lid = threadIdx.x & 31;
    if (lid == 0) { sp[wid] = p; sq[wid] = q; }
    __syncthreads();
    if (threadIdx.x == 0) {
        float P = 0.0f, Q = 0.0f;
        #pragma unroll
        for (int i = 0; i < 8; i++) { P += sp[i]; Q += sq[i]; }
        g_pP[b] = P;
        g_pQ[b] = Q;
    }
}

// ---- main: each block replays the scalar recurrence + streams its tiles ----
__global__ __launch_bounds__(NT)
void clf_main(const float* __restrict__ vL,
              const float* __restrict__ vJ,
              float* __restrict__ out)
{
    const float dt = 0.01f;

    __shared__ float s_alpha[STEPS];
    for (int i = threadIdx.x; i < STEPS; i += NT)
        s_alpha[i] = g_alpha[i];

    // Sum reduction partials (uniform across threads; deterministic order).
    float P = 0.0f, Q = 0.0f;
    #pragma unroll
    for (int i = 0; i < RBLK; i++) { P += g_pP[i]; Q += g_pQ[i]; }
    const float Kq = Q / P;              // the only division, once
    __syncthreads();

    float a = 1.0f, b = 0.0f, c = 1.0f;  // vL = a*vL0 ; vJ = b*vL0 + c*vJ0
    int t_cur = 0;

    const float4* vL4 = (const float4*)vL;
    const float4* vJ4 = (const float4*)vJ;
    float4* outL4 = (float4*)out;
    float4* outJ4 = outL4 + (size_t)STEPS * (DIM / 4);

    int w = blockIdx.x;
    for (int tt = w; tt < NTILES; tt += WRITERS) {
        int chunk = tt / NSLICE;         // chunk-major, so t_cur is monotone
        int slice = tt - chunk * NSLICE;
        int f0    = slice * (NT * 2) + threadIdx.x;
        int t0    = chunk * CHUNK;

        float4 l0 = __ldg(vL4 + f0);
        float4 j0 = __ldg(vJ4 + f0);
        float4 l1 = __ldg(vL4 + f0 + NT);
        float4 j1 = __ldg(vJ4 + f0 + NT);

        // Catch the recurrence up to this chunk (division-free, ~22 cyc/step).
        #pragma unroll 4
        for (; t_cur < t0; t_cur++) {
            float al = s_alpha[t_cur];
            float s  = fmaf(c, Kq, b);                       // = r*a exactly
            float an = a + dt * (al * (s - a) + 0.2f * a);
            float bn = b + dt * (al * (c * Kq) + 0.2f * (a - b));
            float cn = c - dt * ((al + 0.2f) * c);
            a = an; b = bn; c = cn;
        }

        #pragma unroll
        for (int u = 0; u < CHUNK; u++) {
            float al = s_alpha[t0 + u];
            float s  = fmaf(c, Kq, b);
            float an = a + dt * (al * (s - a) + 0.2f * a);
            float bn = b + dt * (al * (c * Kq) + 0.2f * (a - b));
            float cn = c - dt * ((al + 0.2f) * c);
            a = an; b = bn; c = cn;

            float4 oL0 = make_float4(a * l0.x, a * l0.y, a * l0.z, a * l0.w);
            float4 oL1 = make_float4(a * l1.x, a * l1.y, a * l1.z, a * l1.w);
            float4 oJ0 = make_float4(fmaf(b, l0.x, c * j0.x),
                                     fmaf(b, l0.y, c * j0.y),
                                     fmaf(b, l0.z, c * j0.z),
                                     fmaf(b, l0.w, c * j0.w));
            float4 oJ1 = make_float4(fmaf(b, l1.x, c * j1.x),
                                     fmaf(b, l1.y, c * j1.y),
                                     fmaf(b, l1.z, c * j1.z),
                                     fmaf(b, l1.w, c * j1.w));

            size_t base = (size_t)(t0 + u) * (DIM / 4) + f0;
            __stcs(&outL4[base],      oL0);
            __stcs(&outL4[base + NT], oL1);
            __stcs(&outJ4[base],      oJ0);
            __stcs(&outJ4[base + NT], oJ1);
        }
        t_cur = t0 + CHUNK;
    }
}

extern "C" void kernel_launch(void* const* d_in, const int* in_sizes, int n_in,
                              void* d_out, int out_size)
{
    const float* vL = (const float*)d_in[0];
    const float* vJ = (const float*)d_in[1];
    float* out = (float*)d_out;

    clf_pre<<<RBLK + 1, NT>>>(vL, vJ, out);
    clf_main<<<WRITERS, NT>>>(vL, vJ, out);
}

// round 8
// speedup vs baseline: 1.3006x; 1.2350x over previous
#include <cuda_runtime.h>
#include <cstdint>

// CognitiveLorenzField, closed form. The (a,b,c) recurrence (vL = a*vL0,
// vJ = b*vL0 + c*vJ0) is LINEAR with input-independent coefficients; the only
// runtime scalar is Kq = (vL0.vJ0)/(vL0.vL0). By superposition:
//   a_t = ha[t] + Kq*ga[t],  b_t = hb[t] + Kq*gb[t],  c_t = cc[t]
// with all tables (and the Lorenz z) computed AT COMPILE TIME in double.
// Runtime = one dot-product reduction + a pure streaming-store kernel.

#define DIM       65536
#define STEPS     500
#define NSLICE    32                    // slices of 2048 floats (8KB)
#define TCHUNKS   50
#define CHUNK     10
#define NTILES    (TCHUNKS * NSLICE)    // 1600
#define NT        256
#define WRITERS   592
#define RBLK      64

struct Tabs {
    float ha[STEPS], ga[STEPS], hb[STEPS], gb[STEPS], cc[STEPS], zz[STEPS];
};

static constexpr Tabs make_tabs() {
    Tabs T{};
    double x = 1.0, y = 1.0, z = 1.0;
    double ha = 1.0, hb = 0.0, ga = 0.0, gb = 0.0, c = 1.0;
    const double dt = 0.01;
    for (int t = 0; t < STEPS; t++) {
        double dx = 10.0 * (y - x);
        double dy = x * (28.0 - z) - y;
        double dz = x * y - (8.0 / 3.0) * z;
        x += dt * dx; y += dt * dy; z += dt * dz;
        double al = 1.0 + 0.5 * z;
        // homogeneous part of (a,b); forcing response (Kq coefficient); c
        double ha_n = ha + dt * (al * (hb - ha) + 0.2 * ha);
        double hb_n = hb + dt * (0.2 * (ha - hb));
        double ga_n = ga + dt * (al * (gb + c - ga) + 0.2 * ga);
        double gb_n = gb + dt * (al * c + 0.2 * (ga - gb));
        double c_n  = c - dt * ((al + 0.2) * c);
        ha = ha_n; hb = hb_n; ga = ga_n; gb = gb_n; c = c_n;
        T.ha[t] = (float)ha; T.ga[t] = (float)ga;
        T.hb[t] = (float)hb; T.gb[t] = (float)gb;
        T.cc[t] = (float)c;  T.zz[t] = (float)z;
    }
    return T;
}

__device__ constexpr Tabs G = make_tabs();

__device__ float g_pP[RBLK], g_pQ[RBLK];

// ---- pre-kernel: P,Q partials; block 0 also writes traj_z ----
__global__ __launch_bounds__(NT)
void clf_pre(const float* __restrict__ vL, const float* __restrict__ vJ,
             float* __restrict__ out)
{
    const float4* vL4 = (const float4*)vL;
    const float4* vJ4 = (const float4*)vJ;
    int b = blockIdx.x;
    int k = b * NT + threadIdx.x;        // one float4/thread, 1024 floats/block

    float4 l = vL4[k];
    float4 j = vJ4[k];
    float p = l.x * l.x + l.y * l.y + l.z * l.z + l.w * l.w;
    float q = l.x * j.x + l.y * j.y + l.z * j.z + l.w * j.w;

    #pragma unroll
    for (int off = 16; off > 0; off >>= 1) {
        p += __shfl_down_sync(0xffffffffu, p, off);
        q += __shfl_down_sync(0xffffffffu, q, off);
    }
    __shared__ float sp[8], sq[8];
    int wid = threadIdx.x >> 5, lid = threadIdx.x & 31;
    if (lid == 0) { sp[wid] = p; sq[wid] = q; }
    __syncthreads();
    if (threadIdx.x == 0) {
        float P = 0.0f, Q = 0.0f;
        #pragma unroll
        for (int i = 0; i < 8; i++) { P += sp[i]; Q += sq[i]; }
        g_pP[b] = P;
        g_pQ[b] = Q;
    }

    if (b == 0) {
        float* out_z = out + 2ull * STEPS * DIM;
        for (int i = threadIdx.x; i < STEPS; i += NT)
            out_z[i] = G.zz[i];
    }
}

// ---- main: evaluate closed form into smem, then pure store stream ----
__global__ __launch_bounds__(NT)
void clf_main(const float* __restrict__ vL,
              const float* __restrict__ vJ,
              float* __restrict__ out)
{
    // Deterministic uniform sum of reduction partials.
    float P = 0.0f, Q = 0.0f;
    #pragma unroll
    for (int i = 0; i < RBLK; i++) { P += g_pP[i]; Q += g_pQ[i]; }
    const float Kq = Q / P;

    __shared__ float sa[STEPS], sb[STEPS], sc[STEPS];
    for (int i = threadIdx.x; i < STEPS; i += NT) {
        sa[i] = fmaf(Kq, G.ga[i], G.ha[i]);
        sb[i] = fmaf(Kq, G.gb[i], G.hb[i]);
        sc[i] = G.cc[i];
    }
    __syncthreads();

    const float4* vL4 = (const float4*)vL;
    const float4* vJ4 = (const float4*)vJ;
    float4* outL4 = (float4*)out;
    float4* outJ4 = outL4 + (size_t)STEPS * (DIM / 4);

    for (int tt = blockIdx.x; tt < NTILES; tt += WRITERS) {
        int chunk = tt / NSLICE;
        int slice = tt - chunk * NSLICE;
        int f0    = slice * (NT * 2) + threadIdx.x;
        int t0    = chunk * CHUNK;

        float4 l0 = __ldg(vL4 + f0);
        float4 j0 = __ldg(vJ4 + f0);
        float4 l1 = __ldg(vL4 + f0 + NT);
        float4 j1 = __ldg(vJ4 + f0 + NT);

        #pragma unroll
        for (int u = 0; u < CHUNK; u++) {
            int t = t0 + u;
            float a = sa[t], b = sb[t], c = sc[t];

            float4 oL0 = make_float4(a * l0.x, a * l0.y, a * l0.z, a * l0.w);
            float4 oL1 = make_float4(a * l1.x, a * l1.y, a * l1.z, a * l1.w);
            float4 oJ0 = make_float4(fmaf(b, l0.x, c * j0.x),
                                     fmaf(b, l0.y, c * j0.y),
                                     fmaf(b, l0.z, c * j0.z),
                                     fmaf(b, l0.w, c * j0.w));
            float4 oJ1 = make_float4(fmaf(b, l1.x, c * j1.x),
                                     fmaf(b, l1.y, c * j1.y),
                                     fmaf(b, l1.z, c * j1.z),
                                     fmaf(b, l1.w, c * j1.w));

            size_t base = (size_t)t * (DIM / 4) + f0;
            __stcs(&outL4[base],      oL0);
            __stcs(&outL4[base + NT], oL1);
            __stcs(&outJ4[base],      oJ0);
            __stcs(&outJ4[base + NT], oJ1);
        }
    }
}

extern "C" void kernel_launch(void* const* d_in, const int* in_sizes, int n_in,
                              void* d_out, int out_size)
{
    const float* vL = (const float*)d_in[0];
    const float* vJ = (const float*)d_in[1];
    float* out = (float*)d_out;

    clf_pre<<<RBLK, NT>>>(vL, vJ, out);
    clf_main<<<WRITERS, NT>>>(vL, vJ, out);
}

// round 9
// speedup vs baseline: 1.3123x; 1.0090x over previous
#include <cuda_runtime.h>
#include <cstdint>

// CognitiveLorenzField, closed form, SINGLE kernel. Dynamics are linear in the
// one runtime scalar Kq = (vL0.vJ0)/(vL0.vL0):
//   a_t = ha[t] + Kq*ga[t], b_t = hb[t] + Kq*gb[t], c_t = cc[t]
// with all tables + Lorenz z computed at COMPILE TIME in double.
// R9: fuse the reduction into the main kernel (blocks 0-63 produce partials,
// one-time acquire spin, self-resetting counters for graph replay).

#define DIM       65536
#define STEPS     500
#define NSLICE    32                    // slices of 2048 floats (8KB)
#define TCHUNKS   50
#define CHUNK     10
#define NTILES    (TCHUNKS * NSLICE)    // 1600
#define NT        256
#define WRITERS   592                   // one wave: 4 CTA/SM, all co-resident
#define RBLK      64

struct Tabs {
    float ha[STEPS], ga[STEPS], hb[STEPS], gb[STEPS], cc[STEPS], zz[STEPS];
};

static constexpr Tabs make_tabs() {
    Tabs T{};
    double x = 1.0, y = 1.0, z = 1.0;
    double ha = 1.0, hb = 0.0, ga = 0.0, gb = 0.0, c = 1.0;
    const double dt = 0.01;
    for (int t = 0; t < STEPS; t++) {
        double dx = 10.0 * (y - x);
        double dy = x * (28.0 - z) - y;
        double dz = x * y - (8.0 / 3.0) * z;
        x += dt * dx; y += dt * dy; z += dt * dz;
        double al = 1.0 + 0.5 * z;
        double ha_n = ha + dt * (al * (hb - ha) + 0.2 * ha);
        double hb_n = hb + dt * (0.2 * (ha - hb));
        double ga_n = ga + dt * (al * (gb + c - ga) + 0.2 * ga);
        double gb_n = gb + dt * (al * c + 0.2 * (ga - gb));
        double c_n  = c - dt * ((al + 0.2) * c);
        ha = ha_n; hb = hb_n; ga = ga_n; gb = gb_n; c = c_n;
        T.ha[t] = (float)ha; T.ga[t] = (float)ga;
        T.hb[t] = (float)hb; T.gb[t] = (float)gb;
        T.cc[t] = (float)c;  T.zz[t] = (float)z;
    }
    return T;
}

__device__ constexpr Tabs G = make_tabs();

__device__ float g_pP[RBLK], g_pQ[RBLK];
__device__ int   g_done;                // reducers finished (self-resetting)
__device__ int   g_exit;                // blocks finished (self-resetting)

__device__ __forceinline__ int load_acquire(const int* p) {
    int v;
    asm volatile("ld.acquire.gpu.global.s32 %0, [%1];" : "=r"(v) : "l"(p) : "memory");
    return v;
}

__global__ __launch_bounds__(NT)
void clf_fused(const float* __restrict__ vL,
               const float* __restrict__ vJ,
               float* __restrict__ out)
{
    const int bid = blockIdx.x;
    const float4* vL4 = (const float4*)vL;
    const float4* vJ4 = (const float4*)vJ;

    // ---- phase 0: blocks 0..63 produce P,Q partials ----
    if (bid < RBLK) {
        int k = bid * NT + threadIdx.x;       // 1024 floats per block
        float4 l = vL4[k];
        float4 j = vJ4[k];
        float p = l.x * l.x + l.y * l.y + l.z * l.z + l.w * l.w;
        float q = l.x * j.x + l.y * j.y + l.z * j.z + l.w * j.w;

        #pragma unroll
        for (int off = 16; off > 0; off >>= 1) {
            p += __shfl_down_sync(0xffffffffu, p, off);
            q += __shfl_down_sync(0xffffffffu, q, off);
        }
        __shared__ float sp[8], sq[8];
        int wid = threadIdx.x >> 5, lid = threadIdx.x & 31;
        if (lid == 0) { sp[wid] = p; sq[wid] = q; }
        __syncthreads();
        if (threadIdx.x == 0) {
            float P = 0.0f, Q = 0.0f;
            #pragma unroll
            for (int i = 0; i < 8; i++) { P += sp[i]; Q += sq[i]; }
            g_pP[bid] = P;
            g_pQ[bid] = Q;
            __threadfence();                   // publish partials
            atomicAdd(&g_done, 1);
        }
    }

    // block 0 also emits traj_z (independent of inputs)
    if (bid == 0) {
        float* out_z = out + 2ull * STEPS * DIM;
        for (int i = threadIdx.x; i < STEPS; i += NT)
            out_z[i] = G.zz[i];
    }

    // ---- prefetch first tile while waiting ----
    int tt0   = bid;
    int chunk0 = tt0 / NSLICE;
    int slice0 = tt0 - chunk0 * NSLICE;
    int f_pre  = slice0 * (NT * 2) + threadIdx.x;
    float4 pl0 = __ldg(vL4 + f_pre);
    float4 pj0 = __ldg(vJ4 + f_pre);
    float4 pl1 = __ldg(vL4 + f_pre + NT);
    float4 pj1 = __ldg(vJ4 + f_pre + NT);

    // ---- one-time wait for all partials ----
    if (threadIdx.x == 0) {
        while (load_acquire(&g_done) < RBLK)
            __nanosleep(64);
    }
    __syncthreads();

    // ---- evaluate closed form into smem ----
    float P = 0.0f, Q = 0.0f;
    #pragma unroll
    for (int i = 0; i < RBLK; i++) { P += g_pP[i]; Q += g_pQ[i]; }
    const float Kq = Q / P;

    __shared__ float sa[STEPS], sb[STEPS], sc[STEPS];
    for (int i = threadIdx.x; i < STEPS; i += NT) {
        sa[i] = fmaf(Kq, G.ga[i], G.ha[i]);
        sb[i] = fmaf(Kq, G.gb[i], G.hb[i]);
        sc[i] = G.cc[i];
    }
    __syncthreads();

    // ---- pure streaming stores ----
    float4* outL4 = (float4*)out;
    float4* outJ4 = outL4 + (size_t)STEPS * (DIM / 4);

    for (int tt = bid; tt < NTILES; tt += WRITERS) {
        int chunk = tt / NSLICE;
        int slice = tt - chunk * NSLICE;
        int f0    = slice * (NT * 2) + threadIdx.x;
        int t0    = chunk * CHUNK;

        float4 l0, j0, l1, j1;
        if (tt == tt0) { l0 = pl0; j0 = pj0; l1 = pl1; j1 = pj1; }
        else {
            l0 = __ldg(vL4 + f0);
            j0 = __ldg(vJ4 + f0);
            l1 = __ldg(vL4 + f0 + NT);
            j1 = __ldg(vJ4 + f0 + NT);
        }

        #pragma unroll
        for (int u = 0; u < CHUNK; u++) {
            int t = t0 + u;
            float a = sa[t], b = sb[t], c = sc[t];

            float4 oL0 = make_float4(a * l0.x, a * l0.y, a * l0.z, a * l0.w);
            float4 oL1 = make_float4(a * l1.x, a * l1.y, a * l1.z, a * l1.w);
            float4 oJ0 = make_float4(fmaf(b, l0.x, c * j0.x),
                                     fmaf(b, l0.y, c * j0.y),
                                     fmaf(b, l0.z, c * j0.z),
                                     fmaf(b, l0.w, c * j0.w));
            float4 oJ1 = make_float4(fmaf(b, l1.x, c * j1.x),
                                     fmaf(b, l1.y, c * j1.y),
                                     fmaf(b, l1.z, c * j1.z),
                                     fmaf(b, l1.w, c * j1.w));

            size_t base = (size_t)t * (DIM / 4) + f0;
            __stcs(&outL4[base],      oL0);
            __stcs(&outL4[base + NT], oL1);
            __stcs(&outJ4[base],      oJ0);
            __stcs(&outJ4[base + NT], oJ1);
        }
    }

    // ---- self-reset for next graph replay: last block clears counters ----
    __syncthreads();
    if (threadIdx.x == 0) {
        int v = atomicAdd(&g_exit, 1);
        if (v == WRITERS - 1) {
            g_done = 0;
            g_exit = 0;
            __threadfence();
        }
    }
}

extern "C" void kernel_launch(void* const* d_in, const int* in_sizes, int n_in,
                              void* d_out, int out_size)
{
    const float* vL = (const float*)d_in[0];
    const float* vJ = (const float*)d_in[1];
    float* out = (float*)d_out;

    clf_fused<<<WRITERS, NT>>>(vL, vJ, out);
}

// round 10
// speedup vs baseline: 1.3157x; 1.0026x over previous
#include <cuda_runtime.h>
#include <cstdint>

// CognitiveLorenzField, closed form, single fused kernel.
// a_t = ha[t]+Kq*ga[t], b_t = hb[t]+Kq*gb[t], c_t = cc[t]; tables + Lorenz z
// computed at compile time in double. Runtime = dot-product reduction (blocks
// 0..63) + pure streaming stores.
// R10: register diet (1 float4/thread, smem coeffs, incremental addressing)
// -> 8 CTA/SM (2048 thr/SM) to double outstanding-store MLP.

#define DIM       65536
#define STEPS     500
#define NSLICE    64                    // slices of 1024 floats (4KB)
#define TCHUNKS   50
#define CHUNK     10
#define NTILES    (TCHUNKS * NSLICE)    // 3200
#define NT        256
#define WRITERS   1184                  // one wave: 8 CTA/SM
#define RBLK      64

struct Tabs {
    float ha[STEPS], ga[STEPS], hb[STEPS], gb[STEPS], cc[STEPS], zz[STEPS];
};

static constexpr Tabs make_tabs() {
    Tabs T{};
    double x = 1.0, y = 1.0, z = 1.0;
    double ha = 1.0, hb = 0.0, ga = 0.0, gb = 0.0, c = 1.0;
    const double dt = 0.01;
    for (int t = 0; t < STEPS; t++) {
        double dx = 10.0 * (y - x);
        double dy = x * (28.0 - z) - y;
        double dz = x * y - (8.0 / 3.0) * z;
        x += dt * dx; y += dt * dy; z += dt * dz;
        double al = 1.0 + 0.5 * z;
        double ha_n = ha + dt * (al * (hb - ha) + 0.2 * ha);
        double hb_n = hb + dt * (0.2 * (ha - hb));
        double ga_n = ga + dt * (al * (gb + c - ga) + 0.2 * ga);
        double gb_n = gb + dt * (al * c + 0.2 * (ga - gb));
        double c_n  = c - dt * ((al + 0.2) * c);
        ha = ha_n; hb = hb_n; ga = ga_n; gb = gb_n; c = c_n;
        T.ha[t] = (float)ha; T.ga[t] = (float)ga;
        T.hb[t] = (float)hb; T.gb[t] = (float)gb;
        T.cc[t] = (float)c;  T.zz[t] = (float)z;
    }
    return T;
}

__device__ constexpr Tabs G = make_tabs();

__device__ float g_pP[RBLK], g_pQ[RBLK];
__device__ int   g_done;                // reducers finished (self-resetting)
__device__ int   g_exit;                // blocks finished (self-resetting)

__device__ __forceinline__ int load_acquire(const int* p) {
    int v;
    asm volatile("ld.acquire.gpu.global.s32 %0, [%1];" : "=r"(v) : "l"(p) : "memory");
    return v;
}

__global__ __launch_bounds__(NT, 8)
void clf_fused(const float* __restrict__ vL,
               const float* __restrict__ vJ,
               float* __restrict__ out)
{
    const int bid = blockIdx.x;
    const float4* vL4 = (const float4*)vL;
    const float4* vJ4 = (const float4*)vJ;

    // ---- phase 0: blocks 0..63 produce P,Q partials ----
    if (bid < RBLK) {
        int k = bid * NT + threadIdx.x;       // 1024 floats per block
        float4 l = vL4[k];
        float4 j = vJ4[k];
        float p = l.x * l.x + l.y * l.y + l.z * l.z + l.w * l.w;
        float q = l.x * j.x + l.y * j.y + l.z * j.z + l.w * j.w;

        #pragma unroll
        for (int off = 16; off > 0; off >>= 1) {
            p += __shfl_down_sync(0xffffffffu, p, off);
            q += __shfl_down_sync(0xffffffffu, q, off);
        }
        __shared__ float sp[8], sq[8];
        int wid = threadIdx.x >> 5, lid = threadIdx.x & 31;
        if (lid == 0) { sp[wid] = p; sq[wid] = q; }
        __syncthreads();
        if (threadIdx.x == 0) {
            float P = 0.0f, Q = 0.0f;
            #pragma unroll
            for (int i = 0; i < 8; i++) { P += sp[i]; Q += sq[i]; }
            g_pP[bid] = P;
            g_pQ[bid] = Q;
            __threadfence();                   // publish partials
            atomicAdd(&g_done, 1);
        }
    }

    // block 0 also emits traj_z (input-independent)
    if (bid == 0) {
        float* out_z = out + 2ull * STEPS * DIM;
        for (int i = threadIdx.x; i < STEPS; i += NT)
            out_z[i] = G.zz[i];
    }

    // ---- one-time wait for all partials ----
    if (threadIdx.x == 0) {
        while (load_acquire(&g_done) < RBLK)
            __nanosleep(64);
    }
    __syncthreads();

    // ---- evaluate closed form into smem ----
    float P = 0.0f, Q = 0.0f;
    #pragma unroll 16
    for (int i = 0; i < RBLK; i++) { P += g_pP[i]; Q += g_pQ[i]; }
    const float Kq = Q / P;

    __shared__ float sa[STEPS], sb[STEPS], sc[STEPS];
    for (int i = threadIdx.x; i < STEPS; i += NT) {
        sa[i] = fmaf(Kq, G.ga[i], G.ha[i]);
        sb[i] = fmaf(Kq, G.gb[i], G.hb[i]);
        sc[i] = G.cc[i];
    }
    __syncthreads();

    // ---- pure streaming stores (1 float4/thread, 4KB tiles) ----
    float4* outL4 = (float4*)out;
    float4* outJ4 = outL4 + (size_t)STEPS * (DIM / 4);

    for (int tt = bid; tt < NTILES; tt += WRITERS) {
        int chunk = tt >> 6;                  // NSLICE = 64
        int slice = tt & (NSLICE - 1);
        int f0    = slice * NT + threadIdx.x;
        int t0    = chunk * CHUNK;

        float4 l = __ldg(vL4 + f0);
        float4 j = __ldg(vJ4 + f0);

        float4* pL = outL4 + (size_t)t0 * (DIM / 4) + f0;
        float4* pJ = outJ4 + (size_t)t0 * (DIM / 4) + f0;

        #pragma unroll
        for (int u = 0; u < CHUNK; u++) {
            float a = sa[t0 + u], b = sb[t0 + u], c = sc[t0 + u];

            float4 oL = make_float4(a * l.x, a * l.y, a * l.z, a * l.w);
            float4 oJ = make_float4(fmaf(b, l.x, c * j.x),
                                    fmaf(b, l.y, c * j.y),
                                    fmaf(b, l.z, c * j.z),
                                    fmaf(b, l.w, c * j.w));
            __stcs(pL, oL);
            __stcs(pJ, oJ);
            pL += DIM / 4;
            pJ += DIM / 4;
        }
    }

    // ---- self-reset for next graph replay ----
    __syncthreads();
    if (threadIdx.x == 0) {
        int v = atomicAdd(&g_exit, 1);
        if (v == WRITERS - 1) {
            g_done = 0;
            g_exit = 0;
            __threadfence();
        }
    }
}

extern "C" void kernel_launch(void* const* d_in, const int* in_sizes, int n_in,
                              void* d_out, int out_size)
{
    const float* vL = (const float*)d_in[0];
    const float* vJ = (const float*)d_in[1];
    float* out = (float*)d_out;

    clf_fused<<<WRITERS, NT>>>(vL, vJ, out);
}

// round 11
// speedup vs baseline: 1.3659x; 1.0381x over previous
#include <cuda_runtime.h>
#include <cstdint>

// CognitiveLorenzField, closed form, single fused kernel.
// a_t = ha[t]+Kq*ga[t], b_t = hb[t]+Kq*gb[t], c_t = cc[t]; tables + Lorenz z
// computed at compile time in double. Runtime = dot-product reduction (blocks
// 0..63) + pure streaming stores.
// R11: dynamic work-stealing tile loop (atomic counter) to kill the
// 2-vs-3-tile static tail and SM speed-variance stragglers.

#define DIM       65536
#define STEPS     500
#define NSLICE    64                    // slices of 1024 floats (4KB)
#define TCHUNKS   50
#define CHUNK     10
#define NTILES    (TCHUNKS * NSLICE)    // 3200
#define NT        256
#define WRITERS   1184                  // one wave: 8 CTA/SM
#define RBLK      64

struct Tabs {
    float ha[STEPS], ga[STEPS], hb[STEPS], gb[STEPS], cc[STEPS], zz[STEPS];
};

static constexpr Tabs make_tabs() {
    Tabs T{};
    double x = 1.0, y = 1.0, z = 1.0;
    double ha = 1.0, hb = 0.0, ga = 0.0, gb = 0.0, c = 1.0;
    const double dt = 0.01;
    for (int t = 0; t < STEPS; t++) {
        double dx = 10.0 * (y - x);
        double dy = x * (28.0 - z) - y;
        double dz = x * y - (8.0 / 3.0) * z;
        x += dt * dx; y += dt * dy; z += dt * dz;
        double al = 1.0 + 0.5 * z;
        double ha_n = ha + dt * (al * (hb - ha) + 0.2 * ha);
        double hb_n = hb + dt * (0.2 * (ha - hb));
        double ga_n = ga + dt * (al * (gb + c - ga) + 0.2 * ga);
        double gb_n = gb + dt * (al * c + 0.2 * (ga - gb));
        double c_n  = c - dt * ((al + 0.2) * c);
        ha = ha_n; hb = hb_n; ga = ga_n; gb = gb_n; c = c_n;
        T.ha[t] = (float)ha; T.ga[t] = (float)ga;
        T.hb[t] = (float)hb; T.gb[t] = (float)gb;
        T.cc[t] = (float)c;  T.zz[t] = (float)z;
    }
    return T;
}

__device__ constexpr Tabs G = make_tabs();

__device__ float g_pP[RBLK], g_pQ[RBLK];
__device__ int   g_done;                // reducers finished (self-resetting)
__device__ int   g_exit;                // blocks finished (self-resetting)
__device__ int   g_tile = WRITERS;      // next stealable tile (self-resetting)

__device__ __forceinline__ int load_acquire(const int* p) {
    int v;
    asm volatile("ld.acquire.gpu.global.s32 %0, [%1];" : "=r"(v) : "l"(p) : "memory");
    return v;
}

__global__ __launch_bounds__(NT, 8)
void clf_fused(const float* __restrict__ vL,
               const float* __restrict__ vJ,
               float* __restrict__ out)
{
    const int bid = blockIdx.x;
    const float4* vL4 = (const float4*)vL;
    const float4* vJ4 = (const float4*)vJ;

    // ---- phase 0: blocks 0..63 produce P,Q partials ----
    if (bid < RBLK) {
        int k = bid * NT + threadIdx.x;       // 1024 floats per block
        float4 l = vL4[k];
        float4 j = vJ4[k];
        float p = l.x * l.x + l.y * l.y + l.z * l.z + l.w * l.w;
        float q = l.x * j.x + l.y * j.y + l.z * j.z + l.w * j.w;

        #pragma unroll
        for (int off = 16; off > 0; off >>= 1) {
            p += __shfl_down_sync(0xffffffffu, p, off);
            q += __shfl_down_sync(0xffffffffu, q, off);
        }
        __shared__ float sp[8], sq[8];
        int wid = threadIdx.x >> 5, lid = threadIdx.x & 31;
        if (lid == 0) { sp[wid] = p; sq[wid] = q; }
        __syncthreads();
        if (threadIdx.x == 0) {
            float P = 0.0f, Q = 0.0f;
            #pragma unroll
            for (int i = 0; i < 8; i++) { P += sp[i]; Q += sq[i]; }
            g_pP[bid] = P;
            g_pQ[bid] = Q;
            __threadfence();                   // publish partials
            atomicAdd(&g_done, 1);
        }
    }

    // block 0 also emits traj_z (input-independent)
    if (bid == 0) {
        float* out_z = out + 2ull * STEPS * DIM;
        for (int i = threadIdx.x; i < STEPS; i += NT)
            out_z[i] = G.zz[i];
    }

    // ---- prefetch static first tile while waiting ----
    {
        int slice0 = bid & (NSLICE - 1);
        int f_pre  = slice0 * NT + threadIdx.x;
        // touch both operand slices into L1/L2
        (void)__ldg(vL4 + f_pre);
        (void)__ldg(vJ4 + f_pre);
    }

    // ---- one-time wait for all partials ----
    if (threadIdx.x == 0) {
        while (load_acquire(&g_done) < RBLK)
            __nanosleep(64);
    }
    __syncthreads();

    // ---- evaluate closed form into smem ----
    float P = 0.0f, Q = 0.0f;
    #pragma unroll 16
    for (int i = 0; i < RBLK; i++) { P += g_pP[i]; Q += g_pQ[i]; }
    const float Kq = Q / P;

    __shared__ float sa[STEPS], sb[STEPS], sc[STEPS];
    for (int i = threadIdx.x; i < STEPS; i += NT) {
        sa[i] = fmaf(Kq, G.ga[i], G.ha[i]);
        sb[i] = fmaf(Kq, G.gb[i], G.hb[i]);
        sc[i] = G.cc[i];
    }
    __syncthreads();

    // ---- streaming stores with work stealing ----
    float4* outL4 = (float4*)out;
    float4* outJ4 = outL4 + (size_t)STEPS * (DIM / 4);

    __shared__ int s_tt;
    int tt = bid;                             // static first tile (prefetched)
    while (tt < NTILES) {
        int chunk = tt >> 6;                  // NSLICE = 64
        int slice = tt & (NSLICE - 1);
        int f0    = slice * NT + threadIdx.x;
        int t0    = chunk * CHUNK;

        float4 l = __ldg(vL4 + f0);
        float4 j = __ldg(vJ4 + f0);

        float4* pL = outL4 + (size_t)t0 * (DIM / 4) + f0;
        float4* pJ = outJ4 + (size_t)t0 * (DIM / 4) + f0;

        #pragma unroll
        for (int u = 0; u < CHUNK; u++) {
            float a = sa[t0 + u], b = sb[t0 + u], c = sc[t0 + u];

            float4 oL = make_float4(a * l.x, a * l.y, a * l.z, a * l.w);
            float4 oJ = make_float4(fmaf(b, l.x, c * j.x),
                                    fmaf(b, l.y, c * j.y),
                                    fmaf(b, l.z, c * j.z),
                                    fmaf(b, l.w, c * j.w));
            __stcs(pL, oL);
            __stcs(pJ, oJ);
            pL += DIM / 4;
            pJ += DIM / 4;
        }

        if (threadIdx.x == 0)
            s_tt = atomicAdd(&g_tile, 1);     // steal next tile
        __syncthreads();
        tt = s_tt;
        __syncthreads();
    }

    // ---- self-reset for next graph replay ----
    if (threadIdx.x == 0) {
        int v = atomicAdd(&g_exit, 1);
        if (v == WRITERS - 1) {
            g_done = 0;
            g_exit = 0;
            g_tile = WRITERS;
            __threadfence();
        }
    }
}

extern "C" void kernel_launch(void* const* d_in, const int* in_sizes, int n_in,
                              void* d_out, int out_size)
{
    const float* vL = (const float*)d_in[0];
    const float* vJ = (const float*)d_in[1];
    float* out = (float*)d_out;

    clf_fused<<<WRITERS, NT>>>(vL, vJ, out);
}